// round 16
// baseline (speedup 1.0000x reference)
#include <cuda_runtime.h>
#include <cuda_bf16.h>
#include <cuda_fp16.h>
#include <cstdint>
#include <cstddef>

// ---------------------------------------------------------------------------
// MultiHeadAttention: x@W_attn+b -> causal MHA -> @W_proj+b
// B=2, T=2048, C=1024, H=16, D=64.
// Round 16: weights kept [K][N] fp16 (no transpose; prep is pure streaming
// convert); GEMM B fragments via ldsm4t (attention-V pattern). Attention
// unchanged from R15 (3-stage ring, pruning, exp2 softmax).
// ---------------------------------------------------------------------------

#define BB 2
#define TT 2048
#define CC 1024
#define NH 16
#define HD 64
#define MTOT (BB * TT)  // 4096

// ------------------------------ scratch ------------------------------------
__device__ __half g_x16[MTOT * CC];          // x fp16
__device__ __half g_wa[CC * 3 * CC];         // W_attn fp16 [K][3C] (layout kept)
__device__ __half g_wp[CC * CC];             // W_proj fp16 [K][C]
__device__ __half g_y16[MTOT * CC];          // y fp16
__device__ __half g_q16[BB * NH * TT * HD];  // Q*(log2e/8) fp16, head-major
__device__ __half g_k16[BB * NH * TT * HD];  // K fp16
__device__ __half g_v[BB * NH * TT * HD];    // V fp16

// ------------------------------ helpers ------------------------------------
__device__ __forceinline__ uint32_t smem_u32(const void* p) {
    uint32_t a;
    asm("{ .reg .u64 t; cvta.to.shared.u64 t, %1; cvt.u32.u64 %0, t; }"
        : "=r"(a) : "l"(p));
    return a;
}
__device__ __forceinline__ uint32_t swz(uint32_t x) {  // SW128 (128B rows)
    return x ^ ((x >> 3) & 0x70);
}
__device__ __forceinline__ void cp16(uint32_t dst, const void* src) {
    asm volatile("cp.async.cg.shared.global [%0], [%1], 16;"
                 :: "r"(dst), "l"(src));
}
__device__ __forceinline__ void cp_commit() {
    asm volatile("cp.async.commit_group;");
}
template <int N>
__device__ __forceinline__ void cp_wait() {
    asm volatile("cp.async.wait_group %0;" :: "n"(N));
}
__device__ __forceinline__ void ldsm4(uint32_t& r0, uint32_t& r1, uint32_t& r2,
                                      uint32_t& r3, uint32_t addr) {
    asm volatile("ldmatrix.sync.aligned.m8n8.x4.shared.b16 {%0,%1,%2,%3}, [%4];"
                 : "=r"(r0), "=r"(r1), "=r"(r2), "=r"(r3) : "r"(addr));
}
__device__ __forceinline__ void ldsm4t(uint32_t& r0, uint32_t& r1, uint32_t& r2,
                                       uint32_t& r3, uint32_t addr) {
    asm volatile(
        "ldmatrix.sync.aligned.m8n8.x4.trans.shared.b16 {%0,%1,%2,%3}, [%4];"
        : "=r"(r0), "=r"(r1), "=r"(r2), "=r"(r3) : "r"(addr));
}
__device__ __forceinline__ void mma_f16(float* c, const uint32_t* a,
                                        const uint32_t* b) {
    asm volatile(
        "mma.sync.aligned.m16n8k16.row.col.f32.f16.f16.f32 "
        "{%0,%1,%2,%3}, {%4,%5,%6,%7}, {%8,%9}, {%0,%1,%2,%3};"
        : "+f"(c[0]), "+f"(c[1]), "+f"(c[2]), "+f"(c[3])
        : "r"(a[0]), "r"(a[1]), "r"(a[2]), "r"(a[3]), "r"(b[0]), "r"(b[1]));
}
__device__ __forceinline__ uint32_t packh2(float a, float b) {
    __half2 h = __floats2half2_rn(a, b);
    return *reinterpret_cast<uint32_t*>(&h);
}
__device__ __forceinline__ float ex2(float x) {  // 2^x via MUFU only
    float r;
    asm("ex2.approx.ftz.f32 %0, %1;" : "=f"(r) : "f"(x));
    return r;
}

// ---------------------------------------------------------------------------
// prep_kernel: pure streaming fp32->fp16 converts (x, W_attn, W_proj),
// layouts preserved. 2M float4 items over 8192 blocks x 256 threads.
//   idx in [0, 1048576):            x      (4M elems)
//   idx in [1048576, 1835008):      W_attn (3M elems)
//   idx in [1835008, 2097152):      W_proj (1M elems)
// ---------------------------------------------------------------------------
__global__ __launch_bounds__(256) void prep_kernel(
    const float* __restrict__ X, __half* __restrict__ X16,
    const float* __restrict__ Wa, __half* __restrict__ Wa16,
    const float* __restrict__ Wp, __half* __restrict__ Wp16)
{
    const int idx = blockIdx.x * 256 + threadIdx.x;
    const float* src;
    __half* dst;
    int i;
    if (idx < 1048576) {
        src = X; dst = X16; i = idx;
    } else if (idx < 1835008) {
        src = Wa; dst = Wa16; i = idx - 1048576;
    } else {
        src = Wp; dst = Wp16; i = idx - 1835008;
    }
    float4 v = ((const float4*)src)[i];
    ((__half2*)dst)[i * 2 + 0] = __floats2half2_rn(v.x, v.y);
    ((__half2*)dst)[i * 2 + 1] = __floats2half2_rn(v.z, v.w);
}

// ---------------------------------------------------------------------------
// fp16 mma.sync GEMM: C[M,N] = A16[M,K] @ W16[K,N] (+bias), K=1024, NCH=16.
// CTA 128x128, BK=64, 3 stages, 2 CTA/SM, 8 warps (2x4), warp 64x32.
// B stored [K][N]; smem B stage = 2 half-tiles [64k][128B]; fragments via
// ldsm4t (identical pattern to the attention V path).
// EPI=0: fp32 out + bias. EPI=1: QKV epilogue (Q*log2e/8, K, V fp16).
// ---------------------------------------------------------------------------
#define BKB 128
#define TILE_A 16384
#define STAGE 32768
#define NSTAGE 3
#define NCH (CC / 64)  // 16
#define QSCALE 0.1803368801111144f  // 0.125 * log2(e)

template <int EPI>
__global__ __launch_bounds__(256, 2) void gemm_f16_kernel(
    const __half* __restrict__ A, const __half* __restrict__ W16,
    const float* __restrict__ bias, float* __restrict__ Cout,
    __half* __restrict__ Q16, __half* __restrict__ K16,
    __half* __restrict__ Vh, int N)
{
    extern __shared__ char dsm[];
    const uint32_t sbase = smem_u32(dsm);

    const int tid = threadIdx.x;
    const int lane = tid & 31;
    const int warp = tid >> 5;
    const int wm = warp >> 2;
    const int wn = warp & 3;
    const int n0 = blockIdx.x * 128;
    const int m0 = blockIdx.y * 128;

    // A loader: row = tid>>1, 4 x 16B chunks at (tid&1)*64B
    const int ldrow = tid >> 1;
    const int cgrp = (tid & 1) * 4;
    const __half* aRow = A + (size_t)(m0 + ldrow) * CC + cgrp * 8;
    uint32_t dstOffA[4];
#pragma unroll
    for (int j = 0; j < 4; ++j)
        dstOffA[j] = swz(ldrow * BKB + (cgrp + j) * 16);

    // B loader: [K][N] source. 1024 chunks/stage: idx = tid*4+j
    //   half = tid>>7, krow = (tid>>1)&63, cu = (tid&1)*4+j
    const int bhalf = tid >> 7;
    const int bkrow = (tid >> 1) & 63;
    const __half* bRow =
        W16 + (size_t)bkrow * N + n0 + bhalf * 64 + cgrp * 8;  // + c*64*N
    uint32_t dstOffB[4];
#pragma unroll
    for (int j = 0; j < 4; ++j)
        dstOffB[j] = bhalf * 8192 + swz(bkrow * BKB + (cgrp + j) * 16);

#pragma unroll
    for (int c = 0; c < NSTAGE - 1; ++c) {
        const uint32_t sA = sbase + c * STAGE;
        const uint32_t sB = sA + TILE_A;
#pragma unroll
        for (int j = 0; j < 4; ++j) {
            cp16(sA + dstOffA[j], aRow + c * 64 + j * 8);
            cp16(sB + dstOffB[j], bRow + (size_t)c * 64 * N + j * 8);
        }
        cp_commit();
    }

    float acc[4][4][4];
#pragma unroll
    for (int i = 0; i < 4; ++i)
#pragma unroll
        for (int j = 0; j < 4; ++j)
#pragma unroll
            for (int r = 0; r < 4; ++r) acc[i][j][r] = 0.f;

    const int arow = wm * 64 + (lane & 15);
    const uint32_t acolbase = (lane >> 4) << 4;
    // B fragment addressing (ldsm4t, V-path pattern):
    const uint32_t bvRow = (((lane >> 3) & 1) << 3) + (lane & 7);
    const uint32_t bvColB = (lane >> 4) << 4;
    const uint32_t bHalfOff = (wn >> 1) * 8192;    // which 64-col half tile
    const uint32_t bNBase = (wn & 1) * 64;         // byte offset within half

    for (int c = 0; c < NCH; ++c) {
        cp_wait<NSTAGE - 2>();
        __syncthreads();

        if (c + NSTAGE - 1 < NCH) {
            const int cc = c + NSTAGE - 1;
            const uint32_t sA = sbase + (cc % NSTAGE) * STAGE;
            const uint32_t sB = sA + TILE_A;
#pragma unroll
            for (int j = 0; j < 4; ++j) {
                cp16(sA + dstOffA[j], aRow + (size_t)cc * 64 + j * 8);
                cp16(sB + dstOffB[j], bRow + (size_t)cc * 64 * N + j * 8);
            }
        }
        cp_commit();

        const uint32_t sA = sbase + (c % NSTAGE) * STAGE;
        const uint32_t sB = sA + TILE_A + bHalfOff;

#pragma unroll
        for (int kk = 0; kk < 4; ++kk) {
            uint32_t af[4][4], bf[2][4];
#pragma unroll
            for (int fm = 0; fm < 4; ++fm) {
                const int r = arow + fm * 16;
                ldsm4(af[fm][0], af[fm][1], af[fm][2], af[fm][3],
                      sA + swz((uint32_t)r * BKB + kk * 32 + acolbase));
            }
#pragma unroll
            for (int fn2 = 0; fn2 < 2; ++fn2) {
                ldsm4t(bf[fn2][0], bf[fn2][1], bf[fn2][2], bf[fn2][3],
                       sB + swz((kk * 16 + bvRow) * 128 + bNBase + fn2 * 32 +
                                bvColB));
            }
#pragma unroll
            for (int fm = 0; fm < 4; ++fm)
#pragma unroll
                for (int fn = 0; fn < 4; ++fn)
                    mma_f16(acc[fm][fn], af[fm], &bf[fn >> 1][(fn & 1) * 2]);
        }
    }

    // epilogue
#pragma unroll
    for (int fm = 0; fm < 4; ++fm) {
        const int r0 = m0 + wm * 64 + fm * 16 + (lane >> 2);
#pragma unroll
        for (int fn = 0; fn < 4; ++fn) {
            const int cidx = n0 + wn * 32 + fn * 8 + (lane & 3) * 2;
            const float b0 = bias[cidx], b1 = bias[cidx + 1];
            float v00 = acc[fm][fn][0] + b0, v01 = acc[fm][fn][1] + b1;
            float v10 = acc[fm][fn][2] + b0, v11 = acc[fm][fn][3] + b1;
            if (EPI == 0) {
                *(float2*)&Cout[(size_t)r0 * N + cidx] = make_float2(v00, v01);
                *(float2*)&Cout[(size_t)(r0 + 8) * N + cidx] =
                    make_float2(v10, v11);
            } else {
                const int reg = cidx >> 10;
                const int idx = cidx & 1023;
                const int h = idx >> 6, d = idx & 63;
#pragma unroll
                for (int rr = 0; rr < 2; ++rr) {
                    const int m = r0 + rr * 8;
                    const int bb = m >> 11, t = m & 2047;
                    float va = rr ? v10 : v00;
                    float vb = rr ? v11 : v01;
                    const size_t off =
                        ((size_t)(bb * NH + h) * TT + t) * HD + d;
                    if (reg == 0) {
                        *(__half2*)&Q16[off] =
                            __floats2half2_rn(va * QSCALE, vb * QSCALE);
                    } else if (reg == 1) {
                        *(__half2*)&K16[off] = __floats2half2_rn(va, vb);
                    } else {
                        *(__half2*)&Vh[off] = __floats2half2_rn(va, vb);
                    }
                }
            }
        }
    }
}

// ---------------------------------------------------------------------------
// Flash attention (unchanged from R15): all-fp16 mma.sync, single-term QK,
// exp2 softmax, 3-stage K/V ring, exact diagonal pruning.
// smem: Q(16K) | 3 stages x [K16 8K | V 8K] = 64K (+pad).
// ---------------------------------------------------------------------------
#define AQ16 0
#define ASTG 16384
#define STGB 16384
#define ATT_SMEM (ASTG + 3 * STGB + 1024)

__global__ __launch_bounds__(256, 2) void attn_mma_kernel(
    const __half* __restrict__ Q16, const __half* __restrict__ K16,
    const __half* __restrict__ V, __half* __restrict__ Y16)
{
    extern __shared__ char dsm[];
    const uint32_t dbase = smem_u32(dsm);
    const uint32_t sb = (dbase + 1023) & ~1023u;

    const int tid = threadIdx.x;
    const int lane = tid & 31;
    const int w = tid >> 5;
    const int qt = (int)gridDim.x - 1 - (int)blockIdx.x;
    const int bh = blockIdx.y;

    const size_t headbase = (size_t)bh * TT * HD;
    const __half* Qg = Q16 + headbase + (size_t)qt * 128 * HD;
    const __half* Kg = K16 + headbase;
    const __half* Vg = V + headbase;

    const int nkt = 2 * qt + 2;

#pragma unroll
    for (int i = 0; i < 4; ++i) {
        const int c = tid + i * 256;
        const int row = c >> 3, cu = c & 7;
        cp16(sb + AQ16 + swz(row * 128 + cu * 16), Qg + row * HD + cu * 8);
    }
#pragma unroll
    for (int s = 0; s < 2; ++s) {
        const uint32_t stg = sb + ASTG + s * STGB;
        const size_t kbase = (size_t)s * 64 * HD;
#pragma unroll
        for (int i = 0; i < 2; ++i) {
            const int c = tid + i * 256;
            const int row = c >> 3, cu = c & 7;
            const uint32_t so = swz(row * 128 + cu * 16);
            const size_t go = kbase + (size_t)row * HD + cu * 8;
            cp16(stg + so, Kg + go);
            cp16(stg + 8192 + so, Vg + go);
        }
        cp_commit();
    }

    float oc[8][4];
#pragma unroll
    for (int f = 0; f < 8; ++f)
#pragma unroll
        for (int r = 0; r < 4; ++r) oc[f][r] = 0.f;
    float m0 = -1e30f, m1 = -1e30f, l0 = 0.f, l1 = 0.f;

    const uint32_t aBase = (uint32_t)((w * 16 + (lane & 15)) * 128 +
                                      ((lane >> 4) << 4));
    const uint32_t bRow = ((lane >> 4) << 3) + (lane & 7);
    const uint32_t bColB = ((lane >> 3) & 1) << 4;
    const uint32_t vRow = (((lane >> 3) & 1) << 3) + (lane & 7);
    const uint32_t vColB = (lane >> 4) << 4;
    const int rqhi = qt * 128 + w * 16 + 15;

    for (int kt = 0; kt < nkt; ++kt) {
        cp_wait<1>();
        __syncthreads();

        if (kt + 2 < nkt) {
            const int s2 = (kt + 2) % 3;
            const uint32_t stg = sb + ASTG + s2 * STGB;
            const size_t kbase = (size_t)(kt + 2) * 64 * HD;
#pragma unroll
            for (int i = 0; i < 2; ++i) {
                const int c = tid + i * 256;
                const int row = c >> 3, cu = c & 7;
                const uint32_t so = swz(row * 128 + cu * 16);
                const size_t go = kbase + (size_t)row * HD + cu * 8;
                cp16(stg + so, Kg + go);
                cp16(stg + 8192 + so, Vg + go);
            }
        }
        cp_commit();

        const uint32_t stg = sb + ASTG + (kt % 3) * STGB;
        const int rel = rqhi - kt * 64;
        const bool act = rel >= 0;

        if (act) {
            int fLim = 7, kbLim = 3;
            if (kt >= 2 * qt) {
                fLim = rel >> 3; if (fLim > 7) fLim = 7;
                kbLim = rel >> 4; if (kbLim > 3) kbLim = 3;
            }

            float sc[8][4];
#pragma unroll
            for (int f = 0; f < 8; ++f)
#pragma unroll
                for (int r = 0; r < 4; ++r) sc[f][r] = 0.f;

#pragma unroll
            for (int kk = 0; kk < 4; ++kk) {
                uint32_t bk[4][4];
#pragma unroll
                for (int g = 0; g < 4; ++g)
                    if (g * 2 <= fLim)
                        ldsm4(bk[g][0], bk[g][1], bk[g][2], bk[g][3],
                              stg + swz((g * 16 + bRow) * 128 + kk * 32 +
                                        bColB));
                uint32_t aq[4];
                ldsm4(aq[0], aq[1], aq[2], aq[3],
                      sb + AQ16 + swz(aBase + kk * 32));
#pragma unroll
                for (int f = 0; f < 8; ++f)
                    if (f <= fLim)
                        mma_f16(sc[f], aq, &bk[f >> 1][(f & 1) * 2]);
            }

            if (kt >= 2 * qt) {
                const int rq = qt * 128 + w * 16 + (lane >> 2);
#pragma unroll
                for (int f = 0; f < 8; ++f) {
                    const int cg = kt * 64 + f * 8 + 2 * (lane & 3);
                    if (cg > rq) sc[f][0] = -1e30f;
                    if (cg + 1 > rq) sc[f][1] = -1e30f;
                    if (cg > rq + 8) sc[f][2] = -1e30f;
                    if (cg + 1 > rq + 8) sc[f][3] = -1e30f;
                }
            }

            float mx0 = -1e30f, mx1 = -1e30f;
#pragma unroll
            for (int f = 0; f < 8; ++f) {
                mx0 = fmaxf(mx0, fmaxf(sc[f][0], sc[f][1]));
                mx1 = fmaxf(mx1, fmaxf(sc[f][2], sc[f][3]));
            }
            mx0 = fmaxf(mx0, __shfl_xor_sync(0xffffffffu, mx0, 1));
            mx0 = fmaxf(mx0, __shfl_xor_sync(0xffffffffu, mx0, 2));
            mx1 = fmaxf(mx1, __shfl_xor_sync(0xffffffffu, mx1, 1));
            mx1 = fmaxf(mx1, __shfl_xor_sync(0xffffffffu, mx1, 2));
            const float mn0 = fmaxf(m0, mx0), mn1 = fmaxf(m1, mx1);
            const float al0 = ex2(m0 - mn0), al1 = ex2(m1 - mn1);
            float rs0 = 0.f, rs1 = 0.f;
#pragma unroll
            for (int f = 0; f < 8; ++f) {
                sc[f][0] = ex2(sc[f][0] - mn0);
                sc[f][1] = ex2(sc[f][1] - mn0);
                sc[f][2] = ex2(sc[f][2] - mn1);
                sc[f][3] = ex2(sc[f][3] - mn1);
                rs0 += sc[f][0] + sc[f][1];
                rs1 += sc[f][2] + sc[f][3];
            }
            rs0 += __shfl_xor_sync(0xffffffffu, rs0, 1);
            rs0 += __shfl_xor_sync(0xffffffffu, rs0, 2);
            rs1 += __shfl_xor_sync(0xffffffffu, rs1, 1);
            rs1 += __shfl_xor_sync(0xffffffffu, rs1, 2);
            m0 = mn0; m1 = mn1;
            l0 = l0 * al0 + rs0;
            l1 = l1 * al1 + rs1;
#pragma unroll
            for (int f = 0; f < 8; ++f) {
                oc[f][0] *= al0; oc[f][1] *= al0;
                oc[f][2] *= al1; oc[f][3] *= al1;
            }

            uint32_t pa[4][4];
#pragma unroll
            for (int j = 0; j < 4; ++j) {
                pa[j][0] = packh2(sc[2 * j][0], sc[2 * j][1]);
                pa[j][1] = packh2(sc[2 * j][2], sc[2 * j][3]);
                pa[j][2] = packh2(sc[2 * j + 1][0], sc[2 * j + 1][1]);
                pa[j][3] = packh2(sc[2 * j + 1][2], sc[2 * j + 1][3]);
            }

#pragma unroll
            for (int kb = 0; kb < 4; ++kb) {
                if (kb > kbLim) break;
                uint32_t bv[4][4];
#pragma unroll
                for (int g = 0; g < 4; ++g)
                    ldsm4t(bv[g][0], bv[g][1], bv[g][2], bv[g][3],
                           stg + 8192 +
                               swz((kb * 16 + vRow) * 128 + g * 32 + vColB));
#pragma unroll
                for (int f = 0; f < 8; ++f)
                    mma_f16(oc[f], pa[kb], &bv[f >> 1][(f & 1) * 2]);
            }
        }
    }

    const float inv0 = 1.f / l0, inv1 = 1.f / l1;
    const int b = bh >> 4, h = bh & 15;
    const int t0 = qt * 128 + w * 16 + (lane >> 2);
    const size_t mr0 = (size_t)(b * TT + t0) * CC;
    const size_t mr1 = mr0 + (size_t)8 * CC;
#pragma unroll
    for (int f = 0; f < 8; ++f) {
        const int n = h * HD + f * 8 + 2 * (lane & 3);
#pragma unroll
        for (int rr = 0; rr < 2; ++rr) {
            const size_t base = rr ? mr1 : mr0;
            const float va = (rr ? oc[f][2] * inv1 : oc[f][0] * inv0);
            const float vb = (rr ? oc[f][3] * inv1 : oc[f][1] * inv0);
            *(__half2*)&Y16[base + n] = __floats2half2_rn(va, vb);
        }
    }
}

// ---------------------------------------------------------------------------
// launch
// ---------------------------------------------------------------------------
extern "C" void kernel_launch(void* const* d_in, const int* in_sizes, int n_in,
                              void* d_out, int out_size)
{
    (void)in_sizes; (void)n_in; (void)out_size;
    const float* x      = (const float*)d_in[0];
    const float* W_attn = (const float*)d_in[1];
    const float* b_attn = (const float*)d_in[2];
    const float* W_proj = (const float*)d_in[3];
    const float* b_proj = (const float*)d_in[4];
    float* out = (float*)d_out;

    __half *x16, *wa, *wp, *y16, *q16, *k16, *vh;
    cudaGetSymbolAddress((void**)&x16, g_x16);
    cudaGetSymbolAddress((void**)&wa, g_wa);
    cudaGetSymbolAddress((void**)&wp, g_wp);
    cudaGetSymbolAddress((void**)&y16, g_y16);
    cudaGetSymbolAddress((void**)&q16, g_q16);
    cudaGetSymbolAddress((void**)&k16, g_k16);
    cudaGetSymbolAddress((void**)&vh, g_v);

    cudaFuncSetAttribute(gemm_f16_kernel<1>,
                         cudaFuncAttributeMaxDynamicSharedMemorySize,
                         NSTAGE * STAGE);
    cudaFuncSetAttribute(gemm_f16_kernel<0>,
                         cudaFuncAttributeMaxDynamicSharedMemorySize,
                         NSTAGE * STAGE);
    cudaFuncSetAttribute(attn_mma_kernel,
                         cudaFuncAttributeMaxDynamicSharedMemorySize, ATT_SMEM);

    // 0) prep: pure streaming converts (no transposes)
    prep_kernel<<<8192, 256>>>(x, x16, W_attn, wa, W_proj, wp);
    // 1) QKV GEMM -> Q/K/V fp16, head-major
    {
        dim3 grid(3 * CC / 128, MTOT / 128);  // (24, 32)
        gemm_f16_kernel<1><<<grid, 256, NSTAGE * STAGE>>>(
            x16, wa, b_attn, nullptr, q16, k16, vh, 3 * CC);
    }
    // 2) attention -> y fp16
    {
        dim3 grid(TT / 128, BB * NH);
        attn_mma_kernel<<<grid, 256, ATT_SMEM>>>(q16, k16, vh, y16);
    }
    // 3) out = y @ W_proj + b_proj
    {
        dim3 grid(CC / 128, MTOT / 128);  // (8, 32)
        gemm_f16_kernel<0><<<grid, 256, NSTAGE * STAGE>>>(
            y16, wp, b_proj, out, nullptr, nullptr, nullptr, CC);
    }
}

// round 17
// speedup vs baseline: 1.0262x; 1.0262x over previous
#include <cuda_runtime.h>
#include <cuda_bf16.h>
#include <cuda_fp16.h>
#include <cstdint>
#include <cstddef>

// ---------------------------------------------------------------------------
// MultiHeadAttention: x@W_attn+b -> causal MHA -> @W_proj+b
// B=2, T=2048, C=1024, H=16, D=64.
// Round 17 (= R15 final): single-term fp16 mma.sync everywhere; merged prep;
// attention 3-stage K/V ring + exact diagonal pruning + exp2 softmax.
// ---------------------------------------------------------------------------

#define BB 2
#define TT 2048
#define CC 1024
#define NH 16
#define HD 64
#define MTOT (BB * TT)  // 4096

// ------------------------------ scratch ------------------------------------
__device__ __half g_x16[MTOT * CC];          // x fp16
__device__ __half g_wa[3 * CC * CC];         // W_attn^T fp16 [3C][C]
__device__ __half g_wp[CC * CC];             // W_proj^T fp16 [C][C]
__device__ __half g_y16[MTOT * CC];          // y fp16
__device__ __half g_q16[BB * NH * TT * HD];  // Q*(log2e/8) fp16, head-major
__device__ __half g_k16[BB * NH * TT * HD];  // K fp16
__device__ __half g_v[BB * NH * TT * HD];    // V fp16

// ------------------------------ helpers ------------------------------------
__device__ __forceinline__ uint32_t smem_u32(const void* p) {
    uint32_t a;
    asm("{ .reg .u64 t; cvta.to.shared.u64 t, %1; cvt.u32.u64 %0, t; }"
        : "=r"(a) : "l"(p));
    return a;
}
__device__ __forceinline__ uint32_t swz(uint32_t x) {  // SW128 (128B rows)
    return x ^ ((x >> 3) & 0x70);
}
__device__ __forceinline__ void cp16(uint32_t dst, const void* src) {
    asm volatile("cp.async.cg.shared.global [%0], [%1], 16;"
                 :: "r"(dst), "l"(src));
}
__device__ __forceinline__ void cp_commit() {
    asm volatile("cp.async.commit_group;");
}
template <int N>
__device__ __forceinline__ void cp_wait() {
    asm volatile("cp.async.wait_group %0;" :: "n"(N));
}
__device__ __forceinline__ void ldsm4(uint32_t& r0, uint32_t& r1, uint32_t& r2,
                                      uint32_t& r3, uint32_t addr) {
    asm volatile("ldmatrix.sync.aligned.m8n8.x4.shared.b16 {%0,%1,%2,%3}, [%4];"
                 : "=r"(r0), "=r"(r1), "=r"(r2), "=r"(r3) : "r"(addr));
}
__device__ __forceinline__ void ldsm4t(uint32_t& r0, uint32_t& r1, uint32_t& r2,
                                       uint32_t& r3, uint32_t addr) {
    asm volatile(
        "ldmatrix.sync.aligned.m8n8.x4.trans.shared.b16 {%0,%1,%2,%3}, [%4];"
        : "=r"(r0), "=r"(r1), "=r"(r2), "=r"(r3) : "r"(addr));
}
__device__ __forceinline__ void mma_f16(float* c, const uint32_t* a,
                                        const uint32_t* b) {
    asm volatile(
        "mma.sync.aligned.m16n8k16.row.col.f32.f16.f16.f32 "
        "{%0,%1,%2,%3}, {%4,%5,%6,%7}, {%8,%9}, {%0,%1,%2,%3};"
        : "+f"(c[0]), "+f"(c[1]), "+f"(c[2]), "+f"(c[3])
        : "r"(a[0]), "r"(a[1]), "r"(a[2]), "r"(a[3]), "r"(b[0]), "r"(b[1]));
}
__device__ __forceinline__ uint32_t packh2(float a, float b) {
    __half2 h = __floats2half2_rn(a, b);
    return *reinterpret_cast<uint32_t*>(&h);
}
__device__ __forceinline__ float ex2(float x) {  // 2^x via MUFU only
    float r;
    asm("ex2.approx.ftz.f32 %0, %1;" : "=f"(r) : "f"(x));
    return r;
}

// ---------------------------------------------------------------------------
// prep_kernel: one launch does x->fp16 convert + both weight transposes.
// ---------------------------------------------------------------------------
__device__ __forceinline__ void transpose_tile_f16(
    const float* __restrict__ W, __half* __restrict__ WT, int K, int N,
    int n0, int k0, int tid)
{
    __shared__ float t[32][33];
    const int tx = tid & 31, ty = tid >> 5;  // 32 x 8
#pragma unroll
    for (int i = 0; i < 32; i += 8)
        t[ty + i][tx] = W[(size_t)(k0 + ty + i) * N + n0 + tx];
    __syncthreads();
#pragma unroll
    for (int i = 0; i < 32; i += 8) {
        const int n = n0 + ty + i, k = k0 + tx;
        WT[(size_t)n * K + k] = __float2half_rn(t[tx][ty + i]);
    }
}

__global__ __launch_bounds__(256) void prep_kernel(
    const float* __restrict__ X, __half* __restrict__ X16,
    const float* __restrict__ Wa, __half* __restrict__ WaT,
    const float* __restrict__ Wp, __half* __restrict__ WpT)
{
    const int bid = blockIdx.x;
    const int tid = threadIdx.x;
    if (bid < 4096) {
        const int i = bid * 256 + tid;
        float4 v = ((const float4*)X)[i];
        ((__half2*)X16)[i * 2 + 0] = __floats2half2_rn(v.x, v.y);
        ((__half2*)X16)[i * 2 + 1] = __floats2half2_rn(v.z, v.w);
    } else if (bid < 7168) {
        const int b = bid - 4096;
        transpose_tile_f16(Wa, WaT, CC, 3 * CC, (b % 96) * 32, (b / 96) * 32,
                           tid);
    } else {
        const int b = bid - 7168;
        transpose_tile_f16(Wp, WpT, CC, CC, (b % 32) * 32, (b / 32) * 32, tid);
    }
}

// ---------------------------------------------------------------------------
// fp16 mma.sync GEMM: C = A16 @ B16^T (+bias), K=1024, NCH=16.
// CTA 128x128, BK=64, 3 stages, 2 CTA/SM, 8 warps (2x4), warp 64x32.
// ---------------------------------------------------------------------------
#define BKB 128
#define TILE_A 16384
#define STAGE 32768
#define NSTAGE 3
#define NCH (CC / 64)  // 16
#define QSCALE 0.1803368801111144f  // 0.125 * log2(e)

template <int EPI>
__global__ __launch_bounds__(256, 2) void gemm_f16_kernel(
    const __half* __restrict__ A, const __half* __restrict__ B,
    const float* __restrict__ bias, float* __restrict__ Cout,
    __half* __restrict__ Q16, __half* __restrict__ K16,
    __half* __restrict__ Vh, int N)
{
    extern __shared__ char dsm[];
    const uint32_t sbase = smem_u32(dsm);

    const int tid = threadIdx.x;
    const int lane = tid & 31;
    const int warp = tid >> 5;
    const int wm = warp >> 2;
    const int wn = warp & 3;
    const int n0 = blockIdx.x * 128;
    const int m0 = blockIdx.y * 128;

    const int ldrow = tid >> 1;
    const int cgrp = (tid & 1) * 4;
    const __half* aRow = A + (size_t)(m0 + ldrow) * CC + cgrp * 8;
    const __half* bRow = B + (size_t)(n0 + ldrow) * CC + cgrp * 8;
    uint32_t dstOff[4];
#pragma unroll
    for (int j = 0; j < 4; ++j)
        dstOff[j] = swz(ldrow * BKB + (cgrp + j) * 16);

#pragma unroll
    for (int c = 0; c < NSTAGE - 1; ++c) {
        const uint32_t sA = sbase + c * STAGE;
        const uint32_t sB = sA + TILE_A;
#pragma unroll
        for (int j = 0; j < 4; ++j) {
            cp16(sA + dstOff[j], aRow + c * 64 + j * 8);
            cp16(sB + dstOff[j], bRow + c * 64 + j * 8);
        }
        cp_commit();
    }

    float acc[4][4][4];
#pragma unroll
    for (int i = 0; i < 4; ++i)
#pragma unroll
        for (int j = 0; j < 4; ++j)
#pragma unroll
            for (int r = 0; r < 4; ++r) acc[i][j][r] = 0.f;

    const int arow = wm * 64 + (lane & 15);
    const uint32_t acolbase = (lane >> 4) << 4;
    const int brow = wn * 32 + ((lane >> 4) << 3) + (lane & 7);
    const uint32_t bcolbase = ((lane >> 3) & 1) << 4;

    for (int c = 0; c < NCH; ++c) {
        cp_wait<NSTAGE - 2>();
        __syncthreads();

        if (c + NSTAGE - 1 < NCH) {
            const int cc = c + NSTAGE - 1;
            const uint32_t sA = sbase + (cc % NSTAGE) * STAGE;
            const uint32_t sB = sA + TILE_A;
#pragma unroll
            for (int j = 0; j < 4; ++j) {
                cp16(sA + dstOff[j], aRow + (size_t)cc * 64 + j * 8);
                cp16(sB + dstOff[j], bRow + (size_t)cc * 64 + j * 8);
            }
        }
        cp_commit();

        const uint32_t sA = sbase + (c % NSTAGE) * STAGE;
        const uint32_t sB = sA + TILE_A;

#pragma unroll
        for (int kk = 0; kk < 4; ++kk) {
            uint32_t af[4][4], bf[2][4];
#pragma unroll
            for (int fm = 0; fm < 4; ++fm) {
                const int r = arow + fm * 16;
                ldsm4(af[fm][0], af[fm][1], af[fm][2], af[fm][3],
                      sA + swz((uint32_t)r * BKB + kk * 32 + acolbase));
            }
#pragma unroll
            for (int fn2 = 0; fn2 < 2; ++fn2) {
                const int r = brow + fn2 * 16;
                ldsm4(bf[fn2][0], bf[fn2][1], bf[fn2][2], bf[fn2][3],
                      sB + swz((uint32_t)r * BKB + kk * 32 + bcolbase));
            }
#pragma unroll
            for (int fm = 0; fm < 4; ++fm)
#pragma unroll
                for (int fn = 0; fn < 4; ++fn)
                    mma_f16(acc[fm][fn], af[fm], &bf[fn >> 1][(fn & 1) * 2]);
        }
    }

    // epilogue
#pragma unroll
    for (int fm = 0; fm < 4; ++fm) {
        const int r0 = m0 + wm * 64 + fm * 16 + (lane >> 2);
#pragma unroll
        for (int fn = 0; fn < 4; ++fn) {
            const int cidx = n0 + wn * 32 + fn * 8 + (lane & 3) * 2;
            const float b0 = bias[cidx], b1 = bias[cidx + 1];
            float v00 = acc[fm][fn][0] + b0, v01 = acc[fm][fn][1] + b1;
            float v10 = acc[fm][fn][2] + b0, v11 = acc[fm][fn][3] + b1;
            if (EPI == 0) {
                *(float2*)&Cout[(size_t)r0 * N + cidx] = make_float2(v00, v01);
                *(float2*)&Cout[(size_t)(r0 + 8) * N + cidx] =
                    make_float2(v10, v11);
            } else {
                const int reg = cidx >> 10;
                const int idx = cidx & 1023;
                const int h = idx >> 6, d = idx & 63;
#pragma unroll
                for (int rr = 0; rr < 2; ++rr) {
                    const int m = r0 + rr * 8;
                    const int bb = m >> 11, t = m & 2047;
                    float va = rr ? v10 : v00;
                    float vb = rr ? v11 : v01;
                    const size_t off =
                        ((size_t)(bb * NH + h) * TT + t) * HD + d;
                    if (reg == 0) {
                        *(__half2*)&Q16[off] =
                            __floats2half2_rn(va * QSCALE, vb * QSCALE);
                    } else if (reg == 1) {
                        *(__half2*)&K16[off] = __floats2half2_rn(va, vb);
                    } else {
                        *(__half2*)&Vh[off] = __floats2half2_rn(va, vb);
                    }
                }
            }
        }
    }
}

// ---------------------------------------------------------------------------
// Flash attention, all-fp16 mma.sync, single-term QK, exp2 softmax.
// 3-stage K/V ring: ONE barrier per key tile; prefetch issued AFTER the
// barrier into stage (kt+2)%3 (readers of that stage all passed the barrier).
// smem: Q(16K) | 3 stages x [K16 8K | V 8K] = 64K (+pad).
// ---------------------------------------------------------------------------
#define AQ16 0
#define ASTG 16384
#define STGB 16384
#define ATT_SMEM (ASTG + 3 * STGB + 1024)

__global__ __launch_bounds__(256, 2) void attn_mma_kernel(
    const __half* __restrict__ Q16, const __half* __restrict__ K16,
    const __half* __restrict__ V, __half* __restrict__ Y16)
{
    extern __shared__ char dsm[];
    const uint32_t dbase = smem_u32(dsm);
    const uint32_t sb = (dbase + 1023) & ~1023u;

    const int tid = threadIdx.x;
    const int lane = tid & 31;
    const int w = tid >> 5;
    const int qt = (int)gridDim.x - 1 - (int)blockIdx.x;
    const int bh = blockIdx.y;

    const size_t headbase = (size_t)bh * TT * HD;
    const __half* Qg = Q16 + headbase + (size_t)qt * 128 * HD;
    const __half* Kg = K16 + headbase;
    const __half* Vg = V + headbase;

    const int nkt = 2 * qt + 2;

    // prologue: G0 = Q + tile0, G1 = tile1 (nkt >= 2 always)
#pragma unroll
    for (int i = 0; i < 4; ++i) {
        const int c = tid + i * 256;
        const int row = c >> 3, cu = c & 7;
        cp16(sb + AQ16 + swz(row * 128 + cu * 16), Qg + row * HD + cu * 8);
    }
#pragma unroll
    for (int s = 0; s < 2; ++s) {
        const uint32_t stg = sb + ASTG + s * STGB;
        const size_t kbase = (size_t)s * 64 * HD;
#pragma unroll
        for (int i = 0; i < 2; ++i) {
            const int c = tid + i * 256;
            const int row = c >> 3, cu = c & 7;
            const uint32_t so = swz(row * 128 + cu * 16);
            const size_t go = kbase + (size_t)row * HD + cu * 8;
            cp16(stg + so, Kg + go);
            cp16(stg + 8192 + so, Vg + go);
        }
        cp_commit();
    }

    float oc[8][4];
#pragma unroll
    for (int f = 0; f < 8; ++f)
#pragma unroll
        for (int r = 0; r < 4; ++r) oc[f][r] = 0.f;
    float m0 = -1e30f, m1 = -1e30f, l0 = 0.f, l1 = 0.f;

    const uint32_t aBase = (uint32_t)((w * 16 + (lane & 15)) * 128 +
                                      ((lane >> 4) << 4));
    const uint32_t bRow = ((lane >> 4) << 3) + (lane & 7);
    const uint32_t bColB = ((lane >> 3) & 1) << 4;
    const uint32_t vRow = (((lane >> 3) & 1) << 3) + (lane & 7);
    const uint32_t vColB = (lane >> 4) << 4;
    const int rqhi = qt * 128 + w * 16 + 15;

    for (int kt = 0; kt < nkt; ++kt) {
        cp_wait<1>();      // data for tile kt ready (G(kt+1) may be pending)
        __syncthreads();   // single barrier per tile

        // prefetch tile kt+2 into stage (kt+2)%3 == (kt-1)%3 (safe: all
        // warps passed the barrier, so iter kt-1 readers are done)
        if (kt + 2 < nkt) {
            const int s2 = (kt + 2) % 3;
            const uint32_t stg = sb + ASTG + s2 * STGB;
            const size_t kbase = (size_t)(kt + 2) * 64 * HD;
#pragma unroll
            for (int i = 0; i < 2; ++i) {
                const int c = tid + i * 256;
                const int row = c >> 3, cu = c & 7;
                const uint32_t so = swz(row * 128 + cu * 16);
                const size_t go = kbase + (size_t)row * HD + cu * 8;
                cp16(stg + so, Kg + go);
                cp16(stg + 8192 + so, Vg + go);
            }
        }
        cp_commit();

        const uint32_t stg = sb + ASTG + (kt % 3) * STGB;
        const int rel = rqhi - kt * 64;
        const bool act = rel >= 0;

        if (act) {
            int fLim = 7, kbLim = 3;
            if (kt >= 2 * qt) {
                fLim = rel >> 3; if (fLim > 7) fLim = 7;
                kbLim = rel >> 4; if (kbLim > 3) kbLim = 3;
            }

            // ---- S(log2 units) = Q16 K16^T ----
            float sc[8][4];
#pragma unroll
            for (int f = 0; f < 8; ++f)
#pragma unroll
                for (int r = 0; r < 4; ++r) sc[f][r] = 0.f;

#pragma unroll
            for (int kk = 0; kk < 4; ++kk) {
                uint32_t bk[4][4];
#pragma unroll
                for (int g = 0; g < 4; ++g)
                    if (g * 2 <= fLim)
                        ldsm4(bk[g][0], bk[g][1], bk[g][2], bk[g][3],
                              stg + swz((g * 16 + bRow) * 128 + kk * 32 +
                                        bColB));
                uint32_t aq[4];
                ldsm4(aq[0], aq[1], aq[2], aq[3],
                      sb + AQ16 + swz(aBase + kk * 32));
#pragma unroll
                for (int f = 0; f < 8; ++f)
                    if (f <= fLim)
                        mma_f16(sc[f], aq, &bk[f >> 1][(f & 1) * 2]);
            }

            // ---- causal mask ----
            if (kt >= 2 * qt) {
                const int rq = qt * 128 + w * 16 + (lane >> 2);
#pragma unroll
                for (int f = 0; f < 8; ++f) {
                    const int cg = kt * 64 + f * 8 + 2 * (lane & 3);
                    if (cg > rq) sc[f][0] = -1e30f;
                    if (cg + 1 > rq) sc[f][1] = -1e30f;
                    if (cg > rq + 8) sc[f][2] = -1e30f;
                    if (cg + 1 > rq + 8) sc[f][3] = -1e30f;
                }
            }

            // ---- online softmax in exp2 domain ----
            float mx0 = -1e30f, mx1 = -1e30f;
#pragma unroll
            for (int f = 0; f < 8; ++f) {
                mx0 = fmaxf(mx0, fmaxf(sc[f][0], sc[f][1]));
                mx1 = fmaxf(mx1, fmaxf(sc[f][2], sc[f][3]));
            }
            mx0 = fmaxf(mx0, __shfl_xor_sync(0xffffffffu, mx0, 1));
            mx0 = fmaxf(mx0, __shfl_xor_sync(0xffffffffu, mx0, 2));
            mx1 = fmaxf(mx1, __shfl_xor_sync(0xffffffffu, mx1, 1));
            mx1 = fmaxf(mx1, __shfl_xor_sync(0xffffffffu, mx1, 2));
            const float mn0 = fmaxf(m0, mx0), mn1 = fmaxf(m1, mx1);
            const float al0 = ex2(m0 - mn0), al1 = ex2(m1 - mn1);
            float rs0 = 0.f, rs1 = 0.f;
#pragma unroll
            for (int f = 0; f < 8; ++f) {
                sc[f][0] = ex2(sc[f][0] - mn0);
                sc[f][1] = ex2(sc[f][1] - mn0);
                sc[f][2] = ex2(sc[f][2] - mn1);
                sc[f][3] = ex2(sc[f][3] - mn1);
                rs0 += sc[f][0] + sc[f][1];
                rs1 += sc[f][2] + sc[f][3];
            }
            rs0 += __shfl_xor_sync(0xffffffffu, rs0, 1);
            rs0 += __shfl_xor_sync(0xffffffffu, rs0, 2);
            rs1 += __shfl_xor_sync(0xffffffffu, rs1, 1);
            rs1 += __shfl_xor_sync(0xffffffffu, rs1, 2);
            m0 = mn0; m1 = mn1;
            l0 = l0 * al0 + rs0;
            l1 = l1 * al1 + rs1;
#pragma unroll
            for (int f = 0; f < 8; ++f) {
                oc[f][0] *= al0; oc[f][1] *= al0;
                oc[f][2] *= al1; oc[f][3] *= al1;
            }

            // ---- P (fp16, registers) ----
            uint32_t pa[4][4];
#pragma unroll
            for (int j = 0; j < 4; ++j) {
                pa[j][0] = packh2(sc[2 * j][0], sc[2 * j][1]);
                pa[j][1] = packh2(sc[2 * j][2], sc[2 * j][3]);
                pa[j][2] = packh2(sc[2 * j + 1][0], sc[2 * j + 1][1]);
                pa[j][3] = packh2(sc[2 * j + 1][2], sc[2 * j + 1][3]);
            }

            // ---- O += P V ----
#pragma unroll
            for (int kb = 0; kb < 4; ++kb) {
                if (kb > kbLim) break;
                uint32_t bv[4][4];
#pragma unroll
                for (int g = 0; g < 4; ++g)
                    ldsm4t(bv[g][0], bv[g][1], bv[g][2], bv[g][3],
                           stg + 8192 +
                               swz((kb * 16 + vRow) * 128 + g * 32 + vColB));
#pragma unroll
                for (int f = 0; f < 8; ++f)
                    mma_f16(oc[f], pa[kb], &bv[f >> 1][(f & 1) * 2]);
            }
        }
    }

    const float inv0 = 1.f / l0, inv1 = 1.f / l1;
    const int b = bh >> 4, h = bh & 15;
    const int t0 = qt * 128 + w * 16 + (lane >> 2);
    const size_t mr0 = (size_t)(b * TT + t0) * CC;
    const size_t mr1 = mr0 + (size_t)8 * CC;
#pragma unroll
    for (int f = 0; f < 8; ++f) {
        const int n = h * HD + f * 8 + 2 * (lane & 3);
#pragma unroll
        for (int rr = 0; rr < 2; ++rr) {
            const size_t base = rr ? mr1 : mr0;
            const float va = (rr ? oc[f][2] * inv1 : oc[f][0] * inv0);
            const float vb = (rr ? oc[f][3] * inv1 : oc[f][1] * inv0);
            *(__half2*)&Y16[base + n] = __floats2half2_rn(va, vb);
        }
    }
}

// ---------------------------------------------------------------------------
// launch
// ---------------------------------------------------------------------------
extern "C" void kernel_launch(void* const* d_in, const int* in_sizes, int n_in,
                              void* d_out, int out_size)
{
    (void)in_sizes; (void)n_in; (void)out_size;
    const float* x      = (const float*)d_in[0];
    const float* W_attn = (const float*)d_in[1];
    const float* b_attn = (const float*)d_in[2];
    const float* W_proj = (const float*)d_in[3];
    const float* b_proj = (const float*)d_in[4];
    float* out = (float*)d_out;

    __half *x16, *wa, *wp, *y16, *q16, *k16, *vh;
    cudaGetSymbolAddress((void**)&x16, g_x16);
    cudaGetSymbolAddress((void**)&wa, g_wa);
    cudaGetSymbolAddress((void**)&wp, g_wp);
    cudaGetSymbolAddress((void**)&y16, g_y16);
    cudaGetSymbolAddress((void**)&q16, g_q16);
    cudaGetSymbolAddress((void**)&k16, g_k16);
    cudaGetSymbolAddress((void**)&vh, g_v);

    cudaFuncSetAttribute(gemm_f16_kernel<1>,
                         cudaFuncAttributeMaxDynamicSharedMemorySize,
                         NSTAGE * STAGE);
    cudaFuncSetAttribute(gemm_f16_kernel<0>,
                         cudaFuncAttributeMaxDynamicSharedMemorySize,
                         NSTAGE * STAGE);
    cudaFuncSetAttribute(attn_mma_kernel,
                         cudaFuncAttributeMaxDynamicSharedMemorySize, ATT_SMEM);

    // 0) merged prep: x convert + both weight transposes
    prep_kernel<<<8192, 256>>>(x, x16, W_attn, wa, W_proj, wp);
    // 1) QKV GEMM -> Q/K/V fp16, head-major
    {
        dim3 grid(3 * CC / 128, MTOT / 128);  // (24, 32)
        gemm_f16_kernel<1><<<grid, 256, NSTAGE * STAGE>>>(
            x16, wa, b_attn, nullptr, q16, k16, vh, 3 * CC);
    }
    // 2) attention -> y fp16
    {
        dim3 grid(TT / 128, BB * NH);
        attn_mma_kernel<<<grid, 256, ATT_SMEM>>>(q16, k16, vh, y16);
    }
    // 3) out = y @ W_proj + b_proj
    {
        dim3 grid(CC / 128, MTOT / 128);  // (8, 32)
        gemm_f16_kernel<0><<<grid, 256, NSTAGE * STAGE>>>(
            y16, wp, b_proj, out, nullptr, nullptr, nullptr, CC);
    }
}